// round 1
// baseline (speedup 1.0000x reference)
#include <cuda_runtime.h>
#include <cuda_bf16.h>
#include <cstdint>

#define FULLM 0xFFFFFFFFu

// Problem dims
#define BB 8
#define NNq 4096
#define DD 128
#define KK 1024
#define M_TOTAL (BB*NNq)   // 32768

// GEMM tiling
#define BM 128
#define BN 128
#define STR 136            // padded bf16 row stride in smem (68 words, conflict-free)
#define NCHUNK (KK/BN)     // 8

// smem layout (bytes)
#define XS_BYTES   (BM*STR*2)          // 34816
#define PS_BYTES   (2*BN*STR*2)        // 69632
#define SMEM_BYTES (XS_BYTES + PS_BYTES + BM*4)   // + xsq = 104960

// device scratch (no allocations allowed)
__device__ __nv_bfloat16 g_pbf[KK*DD];
__device__ float g_psq[KK];
__device__ int4  g_cand[M_TOTAL];

__device__ __forceinline__ void cp_async16(void* sdst, const void* gsrc){
    unsigned saddr = (unsigned)__cvta_generic_to_shared(sdst);
    asm volatile("cp.async.cg.shared.global [%0], [%1], 16;\n" :: "r"(saddr), "l"(gsrc));
}
__device__ __forceinline__ void cp_commit(){ asm volatile("cp.async.commit_group;\n"); }
template<int N> __device__ __forceinline__ void cp_wait(){ asm volatile("cp.async.wait_group %0;\n"::"n"(N)); }

__device__ __forceinline__ void mma_bf16(float c[4],
    uint32_t a0,uint32_t a1,uint32_t a2,uint32_t a3, uint32_t b0, uint32_t b1){
  asm volatile("mma.sync.aligned.m16n8k16.row.col.f32.bf16.bf16.f32 "
    "{%0,%1,%2,%3}, {%4,%5,%6,%7}, {%8,%9}, {%0,%1,%2,%3};\n"
    : "+f"(c[0]),"+f"(c[1]),"+f"(c[2]),"+f"(c[3])
    : "r"(a0),"r"(a1),"r"(a2),"r"(a3),"r"(b0),"r"(b1));
}

// maintain sorted-descending top-4 (val,idx)
__device__ __forceinline__ void ins4(float* tv, int* ti, float v, int id){
  if (v > tv[3]){
    tv[3]=v; ti[3]=id;
    if (tv[3]>tv[2]){ float t=tv[2];tv[2]=tv[3];tv[3]=t; int q=ti[2];ti[2]=ti[3];ti[3]=q; }
    if (tv[2]>tv[1]){ float t=tv[1];tv[1]=tv[2];tv[2]=t; int q=ti[1];ti[1]=ti[2];ti[2]=q; }
    if (tv[1]>tv[0]){ float t=tv[0];tv[0]=tv[1];tv[1]=t; int q=ti[0];ti[0]=ti[1];ti[1]=q; }
  }
}

// ---------------------------------------------------------------------------
// Kernel 1: prototypes -> bf16 + psq.  1 warp per prototype row.
// ---------------------------------------------------------------------------
__global__ void __launch_bounds__(256) proto_prep_kernel(const float* __restrict__ p){
  int row  = blockIdx.x*8 + (threadIdx.x>>5);
  int lane = threadIdx.x & 31;
  float4 v = reinterpret_cast<const float4*>(p + (size_t)row*DD)[lane];
  float s = v.x*v.x + v.y*v.y + v.z*v.z + v.w*v.w;
  __nv_bfloat162 b0 = __floats2bfloat162_rn(v.x, v.y);
  __nv_bfloat162 b1 = __floats2bfloat162_rn(v.z, v.w);
  __nv_bfloat162* dst = reinterpret_cast<__nv_bfloat162*>(g_pbf + (size_t)row*DD);
  dst[lane*2]   = b0;
  dst[lane*2+1] = b1;
  #pragma unroll
  for (int o=16;o;o>>=1) s += __shfl_xor_sync(FULLM, s, o);
  if (!lane) g_psq[row] = s;
}

// ---------------------------------------------------------------------------
// Kernel 2: fused GEMM + scores epilogue + per-row top-4 candidate tracking
// CTA: BM=128 rows, loops over all K=1024 prototypes in BN=128 chunks.
// 8 warps, warp tile 64x32 (2 warps in M, 4 in N).
// ---------------------------------------------------------------------------
__global__ void __launch_bounds__(256,1)
gemm_scores_kernel(const float* __restrict__ x, float* __restrict__ scores)
{
  extern __shared__ char smem[];
  __nv_bfloat16* xs    = (__nv_bfloat16*)smem;                 // [BM][STR]
  __nv_bfloat16* ps    = (__nv_bfloat16*)(smem + XS_BYTES);    // 2 x [BN][STR]
  float*         xsq_s = (float*)(smem + XS_BYTES + PS_BYTES); // [BM]

  const int tid  = threadIdx.x;
  const int lane = tid & 31;
  const int wid  = tid >> 5;
  const int wm   = wid >> 2;   // 0..1
  const int wn   = wid & 3;    // 0..3
  const int blockRow = blockIdx.x * BM;

#define LOADP(c_, b_) do {                                            \
    const __nv_bfloat16* _src = g_pbf + (size_t)(c_)*BN*DD;           \
    __nv_bfloat16* _dst = ps + (b_)*BN*STR;                           \
    _Pragma("unroll")                                                 \
    for (int _t=0;_t<8;_t++){                                         \
      int _id = tid + _t*256;                                         \
      int _r = _id >> 4, _cp = _id & 15;                              \
      cp_async16(_dst + _r*STR + _cp*8, _src + _r*DD + _cp*8);        \
    }                                                                 \
    cp_commit();                                                      \
  } while(0)

  // kick off P chunk 0 while we convert x
  LOADP(0, 0);

  // load x tile fp32 -> bf16 smem, compute row sumsq (2 threads per row)
  {
    int r = tid >> 1;
    int h = tid & 1;
    const float4* src = (const float4*)(x + (size_t)(blockRow + r)*DD + h*64);
    float s = 0.f;
    #pragma unroll
    for (int i=0;i<16;i++){
      float4 v = src[i];
      s += v.x*v.x + v.y*v.y + v.z*v.z + v.w*v.w;
      __nv_bfloat162 b0 = __floats2bfloat162_rn(v.x, v.y);
      __nv_bfloat162 b1 = __floats2bfloat162_rn(v.z, v.w);
      *(__nv_bfloat162*)&xs[r*STR + h*64 + i*4]     = b0;
      *(__nv_bfloat162*)&xs[r*STR + h*64 + i*4 + 2] = b1;
    }
    s += __shfl_xor_sync(FULLM, s, 1);
    if (!h) xsq_s[r] = s;
  }
  __syncthreads();

  // per-thread row sumsq values (8 rows per thread)
  float xq[8];
  #pragma unroll
  for (int mf=0;mf<4;mf++)
    #pragma unroll
    for (int h=0;h<2;h++)
      xq[mf*2+h] = xsq_s[wm*64 + mf*16 + h*8 + (lane>>2)];

  // top-4 candidate state: t = 2*x.p - psq (x_sq is row-constant)
  float tv[8][4]; int ti[8][4];
  #pragma unroll
  for (int r=0;r<8;r++)
    #pragma unroll
    for (int j=0;j<4;j++){ tv[r][j] = -1e30f; ti[r][j] = 0; }

  for (int chunk=0; chunk<NCHUNK; chunk++){
    if (chunk+1 < NCHUNK){ LOADP(chunk+1, (chunk+1)&1); cp_wait<1>(); }
    else                  { cp_wait<0>(); }
    __syncthreads();

    const __nv_bfloat16* pb = ps + (chunk&1)*BN*STR;
    float acc[4][4][4];
    #pragma unroll
    for (int mf=0;mf<4;mf++)
      #pragma unroll
      for (int nf=0;nf<4;nf++)
        #pragma unroll
        for (int q=0;q<4;q++) acc[mf][nf][q] = 0.f;

    #pragma unroll
    for (int kt=0;kt<8;kt++){
      const int kb = kt*16 + (lane&3)*2;
      uint32_t a[4][4];
      #pragma unroll
      for (int mf=0;mf<4;mf++){
        int r0 = wm*64 + mf*16 + (lane>>2);
        a[mf][0] = *(const uint32_t*)&xs[ r0     *STR + kb    ];
        a[mf][1] = *(const uint32_t*)&xs[(r0+8)  *STR + kb    ];
        a[mf][2] = *(const uint32_t*)&xs[ r0     *STR + kb + 8];
        a[mf][3] = *(const uint32_t*)&xs[(r0+8)  *STR + kb + 8];
      }
      uint32_t bf[4][2];
      #pragma unroll
      for (int nf=0;nf<4;nf++){
        int n0 = wn*32 + nf*8 + (lane>>2);
        bf[nf][0] = *(const uint32_t*)&pb[n0*STR + kb    ];
        bf[nf][1] = *(const uint32_t*)&pb[n0*STR + kb + 8];
      }
      #pragma unroll
      for (int mf=0;mf<4;mf++)
        #pragma unroll
        for (int nf=0;nf<4;nf++)
          mma_bf16(acc[mf][nf], a[mf][0],a[mf][1],a[mf][2],a[mf][3],
                   bf[nf][0], bf[nf][1]);
    }

    // epilogue: scores = (2*xp - psq) - xsq ; track top-4 of (2*xp - psq)
    const int colBase = chunk*BN + wn*32;
    #pragma unroll
    for (int mf=0;mf<4;mf++){
      #pragma unroll
      for (int h=0;h<2;h++){
        const int rl   = mf*2 + h;
        const int grow = blockRow + wm*64 + mf*16 + h*8 + (lane>>2);
        const float xqv = xq[rl];
        #pragma unroll
        for (int nf=0;nf<4;nf++){
          const int col = colBase + nf*8 + (lane&3)*2;
          float c0 = acc[mf][nf][h*2+0];
          float c1 = acc[mf][nf][h*2+1];
          float t0 = 2.f*c0 - __ldg(&g_psq[col]);
          float t1 = 2.f*c1 - __ldg(&g_psq[col+1]);
          float2 o; o.x = t0 - xqv; o.y = t1 - xqv;
          *(float2*)(scores + (size_t)grow*KK + col) = o;
          ins4(tv[rl], ti[rl], t0, col);
          ins4(tv[rl], ti[rl], t1, col+1);
        }
      }
    }
    __syncthreads();
  }

  // merge top-4 across the 16 threads covering each row (64 cands/row)
  float* mv = (float*)(smem + XS_BYTES);           // reuse ps region
  int*   mi = (int*)  (smem + XS_BYTES + BM*64*4);
  #pragma unroll
  for (int mf=0;mf<4;mf++){
    #pragma unroll
    for (int h=0;h<2;h++){
      int r = wm*64 + mf*16 + h*8 + (lane>>2);
      int base = r*64 + wn*16 + (lane&3)*4;
      #pragma unroll
      for (int j=0;j<4;j++){ mv[base+j] = tv[mf*2+h][j]; mi[base+j] = ti[mf*2+h][j]; }
    }
  }
  __syncthreads();
  if (tid < BM){
    int r = tid;
    float bv[4] = {-1e30f,-1e30f,-1e30f,-1e30f};
    int   bi[4] = {0,0,0,0};
    for (int s=0;s<64;s++) ins4(bv, bi, mv[r*64+s], mi[r*64+s]);
    int4 o; o.x=bi[0]; o.y=bi[1]; o.z=bi[2]; o.w=bi[3];
    g_cand[blockRow + r] = o;
  }
#undef LOADP
}

// ---------------------------------------------------------------------------
// Kernel 3: exact fp32 re-scoring of 4 candidates/row, write matched.
// 1 warp per row. Rounding order matches reference: (x2 + p2) - 2*xp, argmin.
// ---------------------------------------------------------------------------
__global__ void __launch_bounds__(256)
fixup_kernel(const float* __restrict__ x, const float* __restrict__ p,
             float* __restrict__ matched)
{
  int row  = blockIdx.x*8 + (threadIdx.x>>5);
  int lane = threadIdx.x & 31;

  float4 xv = reinterpret_cast<const float4*>(x + (size_t)row*DD)[lane];
  float s = xv.x*xv.x + xv.y*xv.y + xv.z*xv.z + xv.w*xv.w;
  #pragma unroll
  for (int o=16;o;o>>=1) s += __shfl_xor_sync(FULLM, s, o);

  int4 cd = g_cand[row];
  int cands[4] = {cd.x, cd.y, cd.z, cd.w};

  float bt = 1e30f; int bi = 0x7fffffff;
  #pragma unroll
  for (int j=0;j<4;j++){
    int ci = cands[j];
    float4 pv = reinterpret_cast<const float4*>(p + (size_t)ci*DD)[lane];
    float d = xv.x*pv.x + xv.y*pv.y + xv.z*pv.z + xv.w*pv.w;
    #pragma unroll
    for (int o=16;o;o>>=1) d += __shfl_xor_sync(FULLM, d, o);
    float t = (s + g_psq[ci]) - 2.f*d;   // minimize (= maximize score)
    if (t < bt || (t == bt && ci < bi)){ bt = t; bi = ci; }
  }

  float4 pv = reinterpret_cast<const float4*>(p + (size_t)bi*DD)[lane];
  reinterpret_cast<float4*>(matched + (size_t)row*DD)[lane] = pv;
}

// ---------------------------------------------------------------------------
extern "C" void kernel_launch(void* const* d_in, const int* in_sizes, int n_in,
                              void* d_out, int out_size)
{
  const float* x = (const float*)d_in[0];   // [8,4096,128] f32
  const float* p = (const float*)d_in[1];   // [1024,128]   f32
  float* matched = (float*)d_out;                                  // [32768,128]
  float* scores  = (float*)d_out + (size_t)M_TOTAL*DD;             // [32768,1024]

  cudaFuncSetAttribute(gemm_scores_kernel,
                       cudaFuncAttributeMaxDynamicSharedMemorySize, SMEM_BYTES);

  proto_prep_kernel<<<KK/8, 256>>>(p);
  gemm_scores_kernel<<<M_TOTAL/BM, 256, SMEM_BYTES>>>(x, scores);
  fixup_kernel<<<M_TOTAL/8, 256>>>(x, p, matched);
}

// round 3
// speedup vs baseline: 1.1679x; 1.1679x over previous
#include <cuda_runtime.h>
#include <cuda_bf16.h>
#include <cstdint>

#define FULLM 0xFFFFFFFFu

// Problem dims
#define BB 8
#define NNq 4096
#define DD 128
#define KK 1024
#define M_TOTAL (BB*NNq)   // 32768

// GEMM tiling
#define BM 128
#define BN 128
#define STR 136            // padded bf16 row stride (272B): conflict-free
#define NCHUNK (KK/BN)     // 8
#define NTHREADS 512       // 16 warps: 4 (M) x 4 (N), warptile 32x32

// smem layout (bytes)
#define XS_BYTES (BM*STR*2)              // 34816
#define PS_HALF  (BN*STR*2)              // 34816
#define PS_BYTES (2*PS_HALF)             // 69632
#define SMEM_BYTES (XS_BYTES + PS_BYTES + BM*4)   // 104960

// device scratch
__device__ __nv_bfloat16 g_pbf[KK*DD];
__device__ float g_psq[KK];

__device__ __forceinline__ void cp_async16(void* sdst, const void* gsrc){
    unsigned saddr = (unsigned)__cvta_generic_to_shared(sdst);
    asm volatile("cp.async.cg.shared.global [%0], [%1], 16;\n" :: "r"(saddr), "l"(gsrc));
}
__device__ __forceinline__ void cp_commit(){ asm volatile("cp.async.commit_group;\n"); }
template<int N> __device__ __forceinline__ void cp_wait(){ asm volatile("cp.async.wait_group %0;\n"::"n"(N)); }

__device__ __forceinline__ void ldsm_x4(uint32_t&r0,uint32_t&r1,uint32_t&r2,uint32_t&r3,uint32_t saddr){
  asm volatile("ldmatrix.sync.aligned.m8n8.x4.shared.b16 {%0,%1,%2,%3}, [%4];\n"
    : "=r"(r0),"=r"(r1),"=r"(r2),"=r"(r3) : "r"(saddr));
}

__device__ __forceinline__ void mma_bf16(float c[4],
    uint32_t a0,uint32_t a1,uint32_t a2,uint32_t a3, uint32_t b0, uint32_t b1){
  asm volatile("mma.sync.aligned.m16n8k16.row.col.f32.bf16.bf16.f32 "
    "{%0,%1,%2,%3}, {%4,%5,%6,%7}, {%8,%9}, {%0,%1,%2,%3};\n"
    : "+f"(c[0]),"+f"(c[1]),"+f"(c[2]),"+f"(c[3])
    : "r"(a0),"r"(a1),"r"(a2),"r"(a3),"r"(b0),"r"(b1));
}

// sorted-descending top-4 insert. Common path = single compare.
__device__ __forceinline__ void ins4(float* tv, int* ti, float v, int id){
  if (v > tv[3]){
    tv[3]=v; ti[3]=id;
    if (tv[3]>tv[2]){ float t=tv[2];tv[2]=tv[3];tv[3]=t; int q=ti[2];ti[2]=ti[3];ti[3]=q; }
    if (tv[2]>tv[1]){ float t=tv[1];tv[1]=tv[2];tv[2]=t; int q=ti[1];ti[1]=ti[2];ti[2]=q; }
    if (tv[1]>tv[0]){ float t=tv[0];tv[0]=tv[1];tv[1]=t; int q=ti[0];ti[0]=ti[1];ti[1]=q; }
  }
}

// ---------------------------------------------------------------------------
// Kernel 1: prototypes -> bf16 + psq.  1 warp per prototype row.
// ---------------------------------------------------------------------------
__global__ void __launch_bounds__(128) proto_prep_kernel(const float* __restrict__ p){
  int row  = blockIdx.x*4 + (threadIdx.x>>5);
  int lane = threadIdx.x & 31;
  float4 v = reinterpret_cast<const float4*>(p + (size_t)row*DD)[lane];
  float s = v.x*v.x + v.y*v.y + v.z*v.z + v.w*v.w;
  __nv_bfloat162 b0 = __floats2bfloat162_rn(v.x, v.y);
  __nv_bfloat162 b1 = __floats2bfloat162_rn(v.z, v.w);
  __nv_bfloat162* dst = reinterpret_cast<__nv_bfloat162*>(g_pbf + (size_t)row*DD);
  dst[lane*2]   = b0;
  dst[lane*2+1] = b1;
  #pragma unroll
  for (int o=16;o;o>>=1) s += __shfl_xor_sync(FULLM, s, o);
  if (!lane) g_psq[row] = s;
}

// ---------------------------------------------------------------------------
// Kernel 2: fused GEMM + scores + top-4/thread tracking + exact fixup.
// CTA: 128 rows x full K=1024 (8 chunks of 128), 16 warps (4x4), wt 32x32.
// ---------------------------------------------------------------------------
__global__ void __launch_bounds__(NTHREADS,1)
gemm_scores_kernel(const float* __restrict__ x, const float* __restrict__ p,
                   float* __restrict__ scores, float* __restrict__ matched)
{
  extern __shared__ char smem[];
  __nv_bfloat16* xs    = (__nv_bfloat16*)smem;                 // [BM][STR]
  __nv_bfloat16* ps    = (__nv_bfloat16*)(smem + XS_BYTES);    // 2 x [BN][STR]
  float*         xsq_s = (float*)(smem + XS_BYTES + PS_BYTES); // [BM]

  const int tid  = threadIdx.x;
  const int lane = tid & 31;
  const int wid  = tid >> 5;
  const int wm   = wid >> 2;   // 0..3
  const int wn   = wid & 3;    // 0..3
  const int blockRow = blockIdx.x * BM;

  const unsigned smem_u32 = (unsigned)__cvta_generic_to_shared(smem);
  const unsigned xs_u32 = smem_u32;
  const unsigned ps_u32 = smem_u32 + XS_BYTES;

#define LOADP(c_, b_) do {                                            \
    const __nv_bfloat16* _src = g_pbf + (size_t)(c_)*BN*DD;           \
    __nv_bfloat16* _dst = ps + (b_)*BN*STR;                           \
    _Pragma("unroll")                                                 \
    for (int _t=0;_t<4;_t++){                                         \
      int _id = tid + _t*NTHREADS;                                    \
      int _r = _id >> 4, _cp = _id & 15;                              \
      cp_async16(_dst + _r*STR + _cp*8, _src + _r*DD + _cp*8);        \
    }                                                                 \
    cp_commit();                                                      \
  } while(0)

  LOADP(0, 0);

  // x tile fp32 -> bf16 smem + row sumsq (4 threads / row)
  {
    int r = tid >> 2;          // 0..127
    int q = tid & 3;           // quarter of the row
    const float4* src = (const float4*)(x + (size_t)(blockRow + r)*DD + q*32);
    float s = 0.f;
    #pragma unroll
    for (int i=0;i<8;i++){
      float4 v = src[i];
      s += v.x*v.x + v.y*v.y + v.z*v.z + v.w*v.w;
      __nv_bfloat162 b0 = __floats2bfloat162_rn(v.x, v.y);
      __nv_bfloat162 b1 = __floats2bfloat162_rn(v.z, v.w);
      *(__nv_bfloat162*)&xs[r*STR + q*32 + i*4]     = b0;
      *(__nv_bfloat162*)&xs[r*STR + q*32 + i*4 + 2] = b1;
    }
    s += __shfl_xor_sync(FULLM, s, 1);
    s += __shfl_xor_sync(FULLM, s, 2);
    if (!q) xsq_s[r] = s;
  }
  __syncthreads();

  // per-thread row sumsq (4 rows per thread: mf2 x h2)
  float xq[4];
  #pragma unroll
  for (int mf=0;mf<2;mf++)
    #pragma unroll
    for (int h=0;h<2;h++)
      xq[mf*2+h] = xsq_s[wm*32 + mf*16 + h*8 + (lane>>2)];

  // ldmatrix base addresses (bytes)
  unsigned aAddr[2];
  #pragma unroll
  for (int mf=0;mf<2;mf++)
    aAddr[mf] = xs_u32 + ((wm*32 + mf*16 + (lane&15))*STR + (lane>>4)*8)*2;
  unsigned bOff[2];
  #pragma unroll
  for (int nfp=0;nfp<2;nfp++)
    bOff[nfp] = ((wn*32 + nfp*16 + (lane>>4)*8 + (lane&7))*STR + ((lane>>3)&1)*8)*2;

  // top-4 per thread per row (Round-1-validated depth)
  float tv[4][4]; int ti[4][4];
  #pragma unroll
  for (int r=0;r<4;r++)
    #pragma unroll
    for (int j=0;j<4;j++){ tv[r][j] = -1e30f; ti[r][j] = 0; }

  for (int chunk=0; chunk<NCHUNK; chunk++){
    if (chunk+1 < NCHUNK){ LOADP(chunk+1, (chunk+1)&1); cp_wait<1>(); }
    else                  { cp_wait<0>(); }
    __syncthreads();

    const unsigned bBase = ps_u32 + (chunk&1)*PS_HALF;

    float acc[2][4][4];
    #pragma unroll
    for (int mf=0;mf<2;mf++)
      #pragma unroll
      for (int nf=0;nf<4;nf++)
        #pragma unroll
        for (int q=0;q<4;q++) acc[mf][nf][q] = 0.f;

    #pragma unroll
    for (int kt=0;kt<8;kt++){
      uint32_t a[2][4], b[2][4];
      #pragma unroll
      for (int mf=0;mf<2;mf++)
        ldsm_x4(a[mf][0],a[mf][1],a[mf][2],a[mf][3], aAddr[mf] + kt*32);
      #pragma unroll
      for (int nfp=0;nfp<2;nfp++)
        ldsm_x4(b[nfp][0],b[nfp][1],b[nfp][2],b[nfp][3], bBase + bOff[nfp] + kt*32);
      #pragma unroll
      for (int mf=0;mf<2;mf++)
        #pragma unroll
        for (int nfp=0;nfp<2;nfp++){
          mma_bf16(acc[mf][2*nfp+0], a[mf][0],a[mf][1],a[mf][2],a[mf][3], b[nfp][0], b[nfp][1]);
          mma_bf16(acc[mf][2*nfp+1], a[mf][0],a[mf][1],a[mf][2],a[mf][3], b[nfp][2], b[nfp][3]);
        }
    }

    // epilogue: scores = (2xp - psq) - xsq ; track top-4 of (2xp - psq)
    const int colBase = chunk*BN + wn*32;
    float2 npq[4];
    #pragma unroll
    for (int nf=0;nf<4;nf++){
      float2 v = *(const float2*)&g_psq[colBase + nf*8 + (lane&3)*2];
      npq[nf].x = -v.x; npq[nf].y = -v.y;
    }
    #pragma unroll
    for (int mf=0;mf<2;mf++){
      #pragma unroll
      for (int h=0;h<2;h++){
        const int rl   = mf*2 + h;
        const int grow = blockRow + wm*32 + mf*16 + h*8 + (lane>>2);
        const float xqv = xq[rl];
        float* srow = scores + (size_t)grow*KK;
        #pragma unroll
        for (int nf=0;nf<4;nf++){
          const int col = colBase + nf*8 + (lane&3)*2;
          float t0 = fmaf(2.f, acc[mf][nf][h*2+0], npq[nf].x);
          float t1 = fmaf(2.f, acc[mf][nf][h*2+1], npq[nf].y);
          float2 o; o.x = t0 - xqv; o.y = t1 - xqv;
          *(float2*)(srow + col) = o;
          ins4(tv[rl], ti[rl], t0, col);
          ins4(tv[rl], ti[rl], t1, col+1);
        }
      }
    }
    __syncthreads();
  }

  // ---- per-row candidate merge (64 cands/row -> top 4) ----
  float* mv = (float*)(smem + XS_BYTES);                 // [128][64] = 32KB
  int*   mi = (int*)  (smem + XS_BYTES + BM*64*4);       // [128][64] = 32KB
  int4*  c4 = (int4*) (smem + XS_BYTES + BM*64*8);       // [128]
  #pragma unroll
  for (int mf=0;mf<2;mf++){
    #pragma unroll
    for (int h=0;h<2;h++){
      int r = wm*32 + mf*16 + h*8 + (lane>>2);
      int base = r*64 + wn*16 + (lane&3)*4;
      #pragma unroll
      for (int j=0;j<4;j++){ mv[base+j] = tv[mf*2+h][j]; mi[base+j] = ti[mf*2+h][j]; }
    }
  }
  __syncthreads();
  if (tid < BM){
    float bv[4] = {-1e30f,-1e30f,-1e30f,-1e30f};
    int   bi[4] = {0,0,0,0};
    for (int s=0;s<64;s++) ins4(bv, bi, mv[tid*64+s], mi[tid*64+s]);
    int4 o; o.x=bi[0]; o.y=bi[1]; o.z=bi[2]; o.w=bi[3];
    c4[tid] = o;
  }
  __syncthreads();

  // ---- exact fp32 fixup: 16 warps x 8 rows, 4 candidates each ----
  #pragma unroll
  for (int rr=0; rr<8; rr++){
    const int r    = wid*8 + rr;
    const int grow = blockRow + r;
    float4 xv = reinterpret_cast<const float4*>(x + (size_t)grow*DD)[lane];
    const float xqe = xsq_s[r];
    int4 cd = c4[r];
    int cands[4] = {cd.x, cd.y, cd.z, cd.w};
    float bt = 1e30f; int bi = 0x7fffffff;
    #pragma unroll
    for (int j=0;j<4;j++){
      int ci = cands[j];
      float4 pv = reinterpret_cast<const float4*>(p + (size_t)ci*DD)[lane];
      float d = xv.x*pv.x + xv.y*pv.y + xv.z*pv.z + xv.w*pv.w;
      #pragma unroll
      for (int o=16;o;o>>=1) d += __shfl_xor_sync(FULLM, d, o);
      float t = (xqe + g_psq[ci]) - 2.f*d;   // minimize
      if (t < bt || (t == bt && ci < bi)){ bt = t; bi = ci; }
    }
    float4 pv = reinterpret_cast<const float4*>(p + (size_t)bi*DD)[lane];
    reinterpret_cast<float4*>(matched + (size_t)grow*DD)[lane] = pv;
  }
#undef LOADP
}

// ---------------------------------------------------------------------------
extern "C" void kernel_launch(void* const* d_in, const int* in_sizes, int n_in,
                              void* d_out, int out_size)
{
  const float* x = (const float*)d_in[0];   // [8,4096,128] f32
  const float* p = (const float*)d_in[1];   // [1024,128]   f32
  float* matched = (float*)d_out;                                  // [32768,128]
  float* scores  = (float*)d_out + (size_t)M_TOTAL*DD;             // [32768,1024]

  cudaFuncSetAttribute(gemm_scores_kernel,
                       cudaFuncAttributeMaxDynamicSharedMemorySize, SMEM_BYTES);

  proto_prep_kernel<<<KK/4, 128>>>(p);
  gemm_scores_kernel<<<M_TOTAL/BM, NTHREADS, SMEM_BYTES>>>(x, p, scores, matched);
}

// round 5
// speedup vs baseline: 1.5951x; 1.3659x over previous
#include <cuda_runtime.h>
#include <cuda_bf16.h>
#include <cstdint>

#define FULLM 0xFFFFFFFFu

// Problem dims
#define DD 128
#define KK 1024
#define M_TOTAL 32768

// GEMM tiling
#define BM 64
#define BN 128
#define STR 136            // padded bf16 row stride (272B): conflict-free
#define NCHUNK (KK/BN)     // 8
#define NTHREADS 256       // 8 warps: 2 (M) x 4 (N), warptile 32x32

// smem layout (bytes)
#define A_OFF    0
#define A_BYTES  (BM*STR*2)             // 17408
#define B_OFF    A_BYTES
#define PS_HALF  (BN*STR*2)             // 34816
#define NPSQ_OFF (B_OFF + 2*PS_HALF)    // 87040
#define XSQ_OFF  (NPSQ_OFF + 4096)      // 91136
#define SMEM_BYTES (XSQ_OFF + 256)      // 91392  (2 CTAs = 182784 <= 227KB/SM)

// device scratch
__device__ __nv_bfloat16 g_pbf[KK*DD];
__device__ float g_psq[KK];
__device__ float g_npsq[KK];

__device__ __forceinline__ void cp_async16(void* sdst, const void* gsrc){
    unsigned saddr = (unsigned)__cvta_generic_to_shared(sdst);
    asm volatile("cp.async.cg.shared.global [%0], [%1], 16;\n" :: "r"(saddr), "l"(gsrc));
}
__device__ __forceinline__ void cp_commit(){ asm volatile("cp.async.commit_group;\n"); }
template<int N> __device__ __forceinline__ void cp_wait(){ asm volatile("cp.async.wait_group %0;\n"::"n"(N)); }

__device__ __forceinline__ void ldsm_x4(uint32_t&r0,uint32_t&r1,uint32_t&r2,uint32_t&r3,uint32_t saddr){
  asm volatile("ldmatrix.sync.aligned.m8n8.x4.shared.b16 {%0,%1,%2,%3}, [%4];\n"
    : "=r"(r0),"=r"(r1),"=r"(r2),"=r"(r3) : "r"(saddr));
}

__device__ __forceinline__ void mma_bf16(float c[4],
    uint32_t a0,uint32_t a1,uint32_t a2,uint32_t a3, uint32_t b0, uint32_t b1){
  asm volatile("mma.sync.aligned.m16n8k16.row.col.f32.bf16.bf16.f32 "
    "{%0,%1,%2,%3}, {%4,%5,%6,%7}, {%8,%9}, {%0,%1,%2,%3};\n"
    : "+f"(c[0]),"+f"(c[1]),"+f"(c[2]),"+f"(c[3])
    : "r"(a0),"r"(a1),"r"(a2),"r"(a3),"r"(b0),"r"(b1));
}

// sorted-descending top-4 insert of packed (value|index) floats.
// Common path = one compare.
__device__ __forceinline__ void ins4v(float* tv, float v){
  if (v > tv[3]){
    tv[3]=v;
    if (tv[3]>tv[2]){ float t=tv[2];tv[2]=tv[3];tv[3]=t; }
    if (tv[2]>tv[1]){ float t=tv[1];tv[1]=tv[2];tv[2]=t; }
    if (tv[1]>tv[0]){ float t=tv[0];tv[0]=tv[1];tv[1]=t; }
  }
}
// pack score value with 10-bit column index in low mantissa bits
__device__ __forceinline__ float packvi(float t, int col){
  return __uint_as_float((__float_as_uint(t) & 0xFFFFFC00u) | (unsigned)col);
}

// ---------------------------------------------------------------------------
// Kernel 1: prototypes -> bf16 + psq/npsq.  1 warp per prototype row.
// ---------------------------------------------------------------------------
__global__ void __launch_bounds__(128) proto_prep_kernel(const float* __restrict__ p){
  int row  = blockIdx.x*4 + (threadIdx.x>>5);
  int lane = threadIdx.x & 31;
  float4 v = reinterpret_cast<const float4*>(p + (size_t)row*DD)[lane];
  float s = v.x*v.x + v.y*v.y + v.z*v.z + v.w*v.w;
  __nv_bfloat162 b0 = __floats2bfloat162_rn(v.x, v.y);
  __nv_bfloat162 b1 = __floats2bfloat162_rn(v.z, v.w);
  __nv_bfloat162* dst = reinterpret_cast<__nv_bfloat162*>(g_pbf + (size_t)row*DD);
  dst[lane*2]   = b0;
  dst[lane*2+1] = b1;
  #pragma unroll
  for (int o=16;o;o>>=1) s += __shfl_xor_sync(FULLM, s, o);
  if (!lane){ g_psq[row] = s; g_npsq[row] = -s; }
}

// ---------------------------------------------------------------------------
// Kernel 2: fused GEMM + scores + packed top-4 tracking + exact fixup.
// CTA: 64 rows x full K=1024 (8 chunks of 128), 8 warps (2x4), wt 32x32.
// 2 CTAs resident per SM.
// ---------------------------------------------------------------------------
__global__ void __launch_bounds__(NTHREADS,2)
gemm_scores_kernel(const float* __restrict__ x, const float* __restrict__ p,
                   float* __restrict__ scores, float* __restrict__ matched)
{
  extern __shared__ char smem[];
  __nv_bfloat16* xs    = (__nv_bfloat16*)(smem + A_OFF);       // [BM][STR]
  __nv_bfloat16* ps    = (__nv_bfloat16*)(smem + B_OFF);       // 2 x [BN][STR]
  float*         npsq_s= (float*)(smem + NPSQ_OFF);            // [KK]
  float*         xsq_s = (float*)(smem + XSQ_OFF);             // [BM]

  const int tid  = threadIdx.x;
  const int lane = tid & 31;
  const int wid  = tid >> 5;
  const int wm   = wid >> 2;   // 0..1
  const int wn   = wid & 3;    // 0..3
  const int blockRow = blockIdx.x * BM;

  const unsigned smem_u32 = (unsigned)__cvta_generic_to_shared(smem);
  const unsigned xs_u32 = smem_u32 + A_OFF;
  const unsigned ps_u32 = smem_u32 + B_OFF;

#define LOADP(c_, b_) do {                                            \
    const __nv_bfloat16* _src = g_pbf + (size_t)(c_)*BN*DD;           \
    __nv_bfloat16* _dst = ps + (b_)*BN*STR;                           \
    _Pragma("unroll")                                                 \
    for (int _t=0;_t<8;_t++){                                         \
      int _id = tid + _t*NTHREADS;                                    \
      int _r = _id >> 4, _cp = _id & 15;                              \
      cp_async16(_dst + _r*STR + _cp*8, _src + _r*DD + _cp*8);        \
    }                                                                 \
    cp_commit();                                                      \
  } while(0)

  LOADP(0, 0);

  // negated psq -> smem (once)
  #pragma unroll
  for (int k=0;k<4;k++) npsq_s[tid + k*NTHREADS] = g_npsq[tid + k*NTHREADS];

  // x tile fp32 -> bf16 smem + row sumsq (4 threads / row)
  {
    int r = tid >> 2;          // 0..63
    int q = tid & 3;
    const float4* src = (const float4*)(x + (size_t)(blockRow + r)*DD + q*32);
    float s = 0.f;
    #pragma unroll
    for (int i=0;i<8;i++){
      float4 v = src[i];
      s += v.x*v.x + v.y*v.y + v.z*v.z + v.w*v.w;
      __nv_bfloat162 b0 = __floats2bfloat162_rn(v.x, v.y);
      __nv_bfloat162 b1 = __floats2bfloat162_rn(v.z, v.w);
      *(__nv_bfloat162*)&xs[r*STR + q*32 + i*4]     = b0;
      *(__nv_bfloat162*)&xs[r*STR + q*32 + i*4 + 2] = b1;
    }
    s += __shfl_xor_sync(FULLM, s, 1);
    s += __shfl_xor_sync(FULLM, s, 2);
    if (!q) xsq_s[r] = s;
  }
  __syncthreads();

  // per-thread row sumsq (4 rows per thread: mf2 x h2)
  float xq[4];
  #pragma unroll
  for (int mf=0;mf<2;mf++)
    #pragma unroll
    for (int h=0;h<2;h++)
      xq[mf*2+h] = xsq_s[wm*32 + mf*16 + h*8 + (lane>>2)];

  // ldmatrix base addresses (bytes)
  unsigned aAddr[2];
  #pragma unroll
  for (int mf=0;mf<2;mf++)
    aAddr[mf] = xs_u32 + ((wm*32 + mf*16 + (lane&15))*STR + (lane>>4)*8)*2;
  unsigned bOff[2];
  #pragma unroll
  for (int nfp=0;nfp<2;nfp++)
    bOff[nfp] = ((wn*32 + nfp*16 + (lane>>4)*8 + (lane&7))*STR + ((lane>>3)&1)*8)*2;

  // packed top-4 per thread per row
  float tv[4][4];
  #pragma unroll
  for (int r=0;r<4;r++)
    #pragma unroll
    for (int j=0;j<4;j++) tv[r][j] = -1e30f;

  for (int chunk=0; chunk<NCHUNK; chunk++){
    if (chunk+1 < NCHUNK){ LOADP(chunk+1, (chunk+1)&1); cp_wait<1>(); }
    else                  { cp_wait<0>(); }
    __syncthreads();

    const unsigned bBase = ps_u32 + (chunk&1)*PS_HALF;

    float acc[2][4][4];
    #pragma unroll
    for (int mf=0;mf<2;mf++)
      #pragma unroll
      for (int nf=0;nf<4;nf++)
        #pragma unroll
        for (int q=0;q<4;q++) acc[mf][nf][q] = 0.f;

    #pragma unroll
    for (int kt=0;kt<8;kt++){
      uint32_t a[2][4], b[2][4];
      #pragma unroll
      for (int mf=0;mf<2;mf++)
        ldsm_x4(a[mf][0],a[mf][1],a[mf][2],a[mf][3], aAddr[mf] + kt*32);
      #pragma unroll
      for (int nfp=0;nfp<2;nfp++)
        ldsm_x4(b[nfp][0],b[nfp][1],b[nfp][2],b[nfp][3], bBase + bOff[nfp] + kt*32);
      #pragma unroll
      for (int mf=0;mf<2;mf++)
        #pragma unroll
        for (int nfp=0;nfp<2;nfp++){
          mma_bf16(acc[mf][2*nfp+0], a[mf][0],a[mf][1],a[mf][2],a[mf][3], b[nfp][0], b[nfp][1]);
          mma_bf16(acc[mf][2*nfp+1], a[mf][0],a[mf][1],a[mf][2],a[mf][3], b[nfp][2], b[nfp][3]);
        }
    }

    // epilogue: scores = (2xp - psq) - xsq ; track packed top-4 of (2xp - psq)
    const int colBase = chunk*BN + wn*32;
    const int cl2 = (lane&3)*2;
    float npq[8];
    #pragma unroll
    for (int nf=0;nf<4;nf++){
      float2 v = *(const float2*)&npsq_s[colBase + nf*8 + cl2];
      npq[2*nf] = v.x; npq[2*nf+1] = v.y;
    }
    #pragma unroll
    for (int mf=0;mf<2;mf++){
      #pragma unroll
      for (int h=0;h<2;h++){
        const int rl   = mf*2 + h;
        const int grow = blockRow + wm*32 + mf*16 + h*8 + (lane>>2);
        const float xqv = xq[rl];
        float* srow = scores + (size_t)grow*KK;
        #pragma unroll
        for (int nf=0;nf<4;nf++){
          const int col = colBase + nf*8 + cl2;
          float t0 = fmaf(2.f, acc[mf][nf][h*2+0], npq[2*nf]);
          float t1 = fmaf(2.f, acc[mf][nf][h*2+1], npq[2*nf+1]);
          float2 o; o.x = t0 - xqv; o.y = t1 - xqv;
          *(float2*)(srow + col) = o;
          ins4v(tv[rl], packvi(t0, col));
          ins4v(tv[rl], packvi(t1, col+1));
        }
      }
    }
    __syncthreads();
  }

  // ---- per-row candidate merge (64 packed cands/row -> top 4) ----
  float* mv = (float*)(smem + A_OFF);              // [64][64] = 16KB
  int4*  c4 = (int4*) (smem + A_OFF + 64*64*4);    // [64]
  #pragma unroll
  for (int mf=0;mf<2;mf++){
    #pragma unroll
    for (int h=0;h<2;h++){
      int r = wm*32 + mf*16 + h*8 + (lane>>2);
      int base = r*64 + wn*16 + (lane&3)*4;
      #pragma unroll
      for (int j=0;j<4;j++) mv[base+j] = tv[mf*2+h][j];
    }
  }
  __syncthreads();
  if (tid < BM){
    float bv[4] = {-1e30f,-1e30f,-1e30f,-1e30f};
    for (int s=0;s<64;s++) ins4v(bv, mv[tid*64+s]);
    int4 o;
    o.x = (int)(__float_as_uint(bv[0]) & 1023u);
    o.y = (int)(__float_as_uint(bv[1]) & 1023u);
    o.z = (int)(__float_as_uint(bv[2]) & 1023u);
    o.w = (int)(__float_as_uint(bv[3]) & 1023u);
    c4[tid] = o;
  }
  __syncthreads();

  // ---- exact fp32 fixup: 8 warps x 8 rows, 4 candidates each ----
  #pragma unroll
  for (int rr=0; rr<8; rr++){
    const int r    = wid*8 + rr;
    const int grow = blockRow + r;
    float4 xv = reinterpret_cast<const float4*>(x + (size_t)grow*DD)[lane];
    const float xqe = xsq_s[r];
    int4 cd = c4[r];
    int cands[4] = {cd.x, cd.y, cd.z, cd.w};
    float bt = 1e30f; int bi = 0x7fffffff;
    #pragma unroll
    for (int j=0;j<4;j++){
      int ci = cands[j];
      float4 pv = reinterpret_cast<const float4*>(p + (size_t)ci*DD)[lane];
      float d = xv.x*pv.x + xv.y*pv.y + xv.z*pv.z + xv.w*pv.w;
      #pragma unroll
      for (int o=16;o;o>>=1) d += __shfl_xor_sync(FULLM, d, o);
      float t = (xqe + g_psq[ci]) - 2.f*d;   // minimize
      if (t < bt || (t == bt && ci < bi)){ bt = t; bi = ci; }
    }
    float4 pv = reinterpret_cast<const float4*>(p + (size_t)bi*DD)[lane];
    reinterpret_cast<float4*>(matched + (size_t)grow*DD)[lane] = pv;
  }
#undef LOADP
}

// ---------------------------------------------------------------------------
extern "C" void kernel_launch(void* const* d_in, const int* in_sizes, int n_in,
                              void* d_out, int out_size)
{
  const float* x = (const float*)d_in[0];   // [8,4096,128] f32
  const float* p = (const float*)d_in[1];   // [1024,128]   f32
  float* matched = (float*)d_out;                                  // [32768,128]
  float* scores  = (float*)d_out + (size_t)M_TOTAL*DD;             // [32768,1024]

  cudaFuncSetAttribute(gemm_scores_kernel,
                       cudaFuncAttributeMaxDynamicSharedMemorySize, SMEM_BYTES);

  proto_prep_kernel<<<KK/4, 128>>>(p);
  gemm_scores_kernel<<<M_TOTAL/BM, NTHREADS, SMEM_BYTES>>>(x, p, scores, matched);
}

// round 6
// speedup vs baseline: 1.6188x; 1.0149x over previous
#include <cuda_runtime.h>
#include <cuda_bf16.h>
#include <cstdint>

#define FULLM 0xFFFFFFFFu

// Problem dims
#define DD 128
#define KK 1024
#define M_TOTAL 32768

// GEMM tiling
#define BM 64
#define BN 64
#define STR 136            // padded bf16 row stride (272B)
#define NCHUNK (KK/BN)     // 16
#define NTHREADS 256       // 8 warps: 2 (M) x 4 (N), warptile 32x16

// smem layout (bytes)
#define A_OFF    0
#define A_BYTES  (BM*STR*2)             // 17408
#define B_OFF    A_BYTES                // ring of 3
#define B_HALF   (BN*STR*2)             // 17408
#define NPSQ_OFF (B_OFF + 3*B_HALF)     // 69632
#define XSQ_OFF  (NPSQ_OFF + 4096)      // 73728
#define SMEM_BYTES (XSQ_OFF + 256)      // 73984 (x2 CTAs = 147968 <= 227KB)

// device scratch
__device__ __nv_bfloat16 g_pbf[KK*DD];
__device__ float g_psq[KK];
__device__ float g_npsq[KK];

__device__ __forceinline__ void cp_async16(void* sdst, const void* gsrc){
    unsigned saddr = (unsigned)__cvta_generic_to_shared(sdst);
    asm volatile("cp.async.cg.shared.global [%0], [%1], 16;\n" :: "r"(saddr), "l"(gsrc));
}
__device__ __forceinline__ void cp_commit(){ asm volatile("cp.async.commit_group;\n"); }
template<int N> __device__ __forceinline__ void cp_wait(){ asm volatile("cp.async.wait_group %0;\n"::"n"(N)); }

__device__ __forceinline__ void ldsm_x4(uint32_t&r0,uint32_t&r1,uint32_t&r2,uint32_t&r3,uint32_t saddr){
  asm volatile("ldmatrix.sync.aligned.m8n8.x4.shared.b16 {%0,%1,%2,%3}, [%4];\n"
    : "=r"(r0),"=r"(r1),"=r"(r2),"=r"(r3) : "r"(saddr));
}

__device__ __forceinline__ void mma_bf16(float c[4],
    uint32_t a0,uint32_t a1,uint32_t a2,uint32_t a3, uint32_t b0, uint32_t b1){
  asm volatile("mma.sync.aligned.m16n8k16.row.col.f32.bf16.bf16.f32 "
    "{%0,%1,%2,%3}, {%4,%5,%6,%7}, {%8,%9}, {%0,%1,%2,%3};\n"
    : "+f"(c[0]),"+f"(c[1]),"+f"(c[2]),"+f"(c[3])
    : "r"(a0),"r"(a1),"r"(a2),"r"(a3),"r"(b0),"r"(b1));
}

// sorted-descending top-4 insert of packed (value|index) floats.
__device__ __forceinline__ void ins4v(float* tv, float v){
  if (v > tv[3]){
    tv[3]=v;
    if (tv[3]>tv[2]){ float t=tv[2];tv[2]=tv[3];tv[3]=t; }
    if (tv[2]>tv[1]){ float t=tv[1];tv[1]=tv[2];tv[2]=t; }
    if (tv[1]>tv[0]){ float t=tv[0];tv[0]=tv[1];tv[1]=t; }
  }
}
__device__ __forceinline__ float packvi(float t, int col){
  return __uint_as_float((__float_as_uint(t) & 0xFFFFFC00u) | (unsigned)col);
}

// ---------------------------------------------------------------------------
// Kernel 1: prototypes -> bf16 + psq/npsq.  1 warp per prototype row.
// ---------------------------------------------------------------------------
__global__ void __launch_bounds__(128) proto_prep_kernel(const float* __restrict__ p){
  int row  = blockIdx.x*4 + (threadIdx.x>>5);
  int lane = threadIdx.x & 31;
  float4 v = reinterpret_cast<const float4*>(p + (size_t)row*DD)[lane];
  float s = v.x*v.x + v.y*v.y + v.z*v.z + v.w*v.w;
  __nv_bfloat162 b0 = __floats2bfloat162_rn(v.x, v.y);
  __nv_bfloat162 b1 = __floats2bfloat162_rn(v.z, v.w);
  __nv_bfloat162* dst = reinterpret_cast<__nv_bfloat162*>(g_pbf + (size_t)row*DD);
  dst[lane*2]   = b0;
  dst[lane*2+1] = b1;
  #pragma unroll
  for (int o=16;o;o>>=1) s += __shfl_xor_sync(FULLM, s, o);
  if (!lane){ g_psq[row] = s; g_npsq[row] = -s; }
}

// ---------------------------------------------------------------------------
// Kernel 2: fused GEMM (A-in-registers) + scores + packed top-4 + exact fixup.
// CTA: 64 rows x K=1024 in 16 chunks of 64. 8 warps (2x4), warptile 32x16.
// 3-stage cp.async ring, one __syncthreads per chunk. 2 CTAs/SM.
// ---------------------------------------------------------------------------
__global__ void __launch_bounds__(NTHREADS,2)
gemm_scores_kernel(const float* __restrict__ x, const float* __restrict__ p,
                   float* __restrict__ scores, float* __restrict__ matched)
{
  extern __shared__ char smem[];
  __nv_bfloat16* xs    = (__nv_bfloat16*)(smem + A_OFF);
  __nv_bfloat16* ps    = (__nv_bfloat16*)(smem + B_OFF);
  float*         npsq_s= (float*)(smem + NPSQ_OFF);
  float*         xsq_s = (float*)(smem + XSQ_OFF);

  const int tid  = threadIdx.x;
  const int lane = tid & 31;
  const int wid  = tid >> 5;
  const int wm   = wid >> 2;   // 0..1
  const int wn   = wid & 3;    // 0..3
  const int blockRow = blockIdx.x * BM;

  const unsigned smem_u32 = (unsigned)__cvta_generic_to_shared(smem);
  const unsigned xs_u32 = smem_u32 + A_OFF;
  const unsigned ps_u32 = smem_u32 + B_OFF;

#define LOADP(c_, b_) do {                                            \
    const __nv_bfloat16* _src = g_pbf + (size_t)(c_)*BN*DD;           \
    __nv_bfloat16* _dst = ps + (b_)*BN*STR;                           \
    _Pragma("unroll")                                                 \
    for (int _t=0;_t<4;_t++){                                         \
      int _id = tid + _t*NTHREADS;                                    \
      int _r = _id >> 4, _cp = _id & 15;                              \
      cp_async16(_dst + _r*STR + _cp*8, _src + _r*DD + _cp*8);        \
    }                                                                 \
    cp_commit();                                                      \
  } while(0)

  LOADP(0, 0);
  LOADP(1, 1);

  // negated psq -> smem (once)
  #pragma unroll
  for (int k=0;k<4;k++) npsq_s[tid + k*NTHREADS] = g_npsq[tid + k*NTHREADS];

  // x tile fp32 -> bf16 smem + row sumsq (4 threads / row)
  {
    int r = tid >> 2;          // 0..63
    int q = tid & 3;
    const float4* src = (const float4*)(x + (size_t)(blockRow + r)*DD + q*32);
    float s = 0.f;
    #pragma unroll
    for (int i=0;i<8;i++){
      float4 v = src[i];
      s += v.x*v.x + v.y*v.y + v.z*v.z + v.w*v.w;
      __nv_bfloat162 b0 = __floats2bfloat162_rn(v.x, v.y);
      __nv_bfloat162 b1 = __floats2bfloat162_rn(v.z, v.w);
      *(__nv_bfloat162*)&xs[r*STR + q*32 + i*4]     = b0;
      *(__nv_bfloat162*)&xs[r*STR + q*32 + i*4 + 2] = b1;
    }
    s += __shfl_xor_sync(FULLM, s, 1);
    s += __shfl_xor_sync(FULLM, s, 2);
    if (!q) xsq_s[r] = s;
  }
  __syncthreads();

  // A fragments for all of K: a[8 ksteps][2 mf][4 regs] = 64 regs, loaded once.
  uint32_t afr[8][2][4];
  {
    unsigned aAddr[2];
    #pragma unroll
    for (int mf=0;mf<2;mf++)
      aAddr[mf] = xs_u32 + ((wm*32 + mf*16 + (lane&15))*STR + (lane>>4)*8)*2;
    #pragma unroll
    for (int kt=0;kt<8;kt++)
      #pragma unroll
      for (int mf=0;mf<2;mf++)
        ldsm_x4(afr[kt][mf][0],afr[kt][mf][1],afr[kt][mf][2],afr[kt][mf][3],
                aAddr[mf] + kt*32);
  }

  // per-thread row sumsq (4 rows per thread: mf2 x h2)
  float xq[4];
  #pragma unroll
  for (int mf=0;mf<2;mf++)
    #pragma unroll
    for (int h=0;h<2;h++)
      xq[mf*2+h] = xsq_s[wm*32 + mf*16 + h*8 + (lane>>2)];

  // B ldmatrix offset within a ring buffer
  const unsigned bOff = ((wn*16 + (lane>>4)*8 + (lane&7))*STR + ((lane>>3)&1)*8)*2;

  // packed top-4 per thread per row
  float tv[4][4];
  #pragma unroll
  for (int r=0;r<4;r++)
    #pragma unroll
    for (int j=0;j<4;j++) tv[r][j] = -1e30f;

  int buf = 0;
  for (int chunk=0; chunk<NCHUNK; chunk++){
    if (chunk < NCHUNK-1) cp_wait<1>(); else cp_wait<0>();
    __syncthreads();
    // prefetch chunk+2 into the buffer last read at iteration chunk-1
    if (chunk+2 < NCHUNK){
      int nb = buf+2; if (nb >= 3) nb -= 3;
      LOADP(chunk+2, nb);
    }

    const unsigned bBase = ps_u32 + buf*B_HALF + bOff;

    float acc[2][2][4];
    #pragma unroll
    for (int mf=0;mf<2;mf++)
      #pragma unroll
      for (int nf=0;nf<2;nf++)
        #pragma unroll
        for (int q=0;q<4;q++) acc[mf][nf][q] = 0.f;

    #pragma unroll
    for (int kt=0;kt<8;kt++){
      uint32_t b[4];
      ldsm_x4(b[0],b[1],b[2],b[3], bBase + kt*32);
      #pragma unroll
      for (int mf=0;mf<2;mf++){
        mma_bf16(acc[mf][0], afr[kt][mf][0],afr[kt][mf][1],afr[kt][mf][2],afr[kt][mf][3], b[0], b[1]);
        mma_bf16(acc[mf][1], afr[kt][mf][0],afr[kt][mf][1],afr[kt][mf][2],afr[kt][mf][3], b[2], b[3]);
      }
    }

    // epilogue: scores = (2xp - psq) - xsq ; track packed top-4 of (2xp - psq)
    const int colBase = chunk*BN + wn*16;
    const int cl2 = (lane&3)*2;
    float npq[4];
    {
      float2 v0 = *(const float2*)&npsq_s[colBase + cl2];
      float2 v1 = *(const float2*)&npsq_s[colBase + 8 + cl2];
      npq[0]=v0.x; npq[1]=v0.y; npq[2]=v1.x; npq[3]=v1.y;
    }
    #pragma unroll
    for (int mf=0;mf<2;mf++){
      #pragma unroll
      for (int h=0;h<2;h++){
        const int rl   = mf*2 + h;
        const int grow = blockRow + wm*32 + mf*16 + h*8 + (lane>>2);
        const float xqv = xq[rl];
        float* srow = scores + (size_t)grow*KK;
        #pragma unroll
        for (int nf=0;nf<2;nf++){
          const int col = colBase + nf*8 + cl2;
          float t0 = fmaf(2.f, acc[mf][nf][h*2+0], npq[2*nf]);
          float t1 = fmaf(2.f, acc[mf][nf][h*2+1], npq[2*nf+1]);
          float2 o; o.x = t0 - xqv; o.y = t1 - xqv;
          *(float2*)(srow + col) = o;
          ins4v(tv[rl], packvi(t0, col));
          ins4v(tv[rl], packvi(t1, col+1));
        }
      }
    }
    buf++; if (buf >= 3) buf -= 3;
  }
  __syncthreads();

  // ---- per-row candidate merge (64 packed cands/row -> top 4) ----
  float* mv = (float*)(smem + A_OFF);              // [64][64] = 16KB
  int4*  c4 = (int4*) (smem + A_OFF + 64*64*4);    // [64]
  #pragma unroll
  for (int mf=0;mf<2;mf++){
    #pragma unroll
    for (int h=0;h<2;h++){
      int r = wm*32 + mf*16 + h*8 + (lane>>2);
      int base = r*64 + wn*16 + (lane&3)*4;
      #pragma unroll
      for (int j=0;j<4;j++) mv[base+j] = tv[mf*2+h][j];
    }
  }
  __syncthreads();
  if (tid < BM){
    float bv[4] = {-1e30f,-1e30f,-1e30f,-1e30f};
    for (int s=0;s<64;s++) ins4v(bv, mv[tid*64+s]);
    int4 o;
    o.x = (int)(__float_as_uint(bv[0]) & 1023u);
    o.y = (int)(__float_as_uint(bv[1]) & 1023u);
    o.z = (int)(__float_as_uint(bv[2]) & 1023u);
    o.w = (int)(__float_as_uint(bv[3]) & 1023u);
    c4[tid] = o;
  }
  __syncthreads();

  // ---- exact fp32 fixup: 8 warps x 8 rows, 4 candidates each ----
  #pragma unroll
  for (int rr=0; rr<8; rr++){
    const int r    = wid*8 + rr;
    const int grow = blockRow + r;
    float4 xv = reinterpret_cast<const float4*>(x + (size_t)grow*DD)[lane];
    const float xqe = xsq_s[r];
    int4 cd = c4[r];
    int cands[4] = {cd.x, cd.y, cd.z, cd.w};
    float bt = 1e30f; int bi = 0x7fffffff;
    #pragma unroll
    for (int j=0;j<4;j++){
      int ci = cands[j];
      float4 pv = reinterpret_cast<const float4*>(p + (size_t)ci*DD)[lane];
      float d = xv.x*pv.x + xv.y*pv.y + xv.z*pv.z + xv.w*pv.w;
      #pragma unroll
      for (int o=16;o;o>>=1) d += __shfl_xor_sync(FULLM, d, o);
      float t = (xqe + g_psq[ci]) - 2.f*d;   // minimize
      if (t < bt || (t == bt && ci < bi)){ bt = t; bi = ci; }
    }
    float4 pv = reinterpret_cast<const float4*>(p + (size_t)bi*DD)[lane];
    reinterpret_cast<float4*>(matched + (size_t)grow*DD)[lane] = pv;
  }
#undef LOADP
}

// ---------------------------------------------------------------------------
extern "C" void kernel_launch(void* const* d_in, const int* in_sizes, int n_in,
                              void* d_out, int out_size)
{
  const float* x = (const float*)d_in[0];   // [8,4096,128] f32
  const float* p = (const float*)d_in[1];   // [1024,128]   f32
  float* matched = (float*)d_out;                                  // [32768,128]
  float* scores  = (float*)d_out + (size_t)M_TOTAL*DD;             // [32768,1024]

  cudaFuncSetAttribute(gemm_scores_kernel,
                       cudaFuncAttributeMaxDynamicSharedMemorySize, SMEM_BYTES);

  proto_prep_kernel<<<KK/4, 128>>>(p);
  gemm_scores_kernel<<<M_TOTAL/BM, NTHREADS, SMEM_BYTES>>>(x, p, scores, matched);
}